// round 15
// baseline (speedup 1.0000x reference)
#include <cuda_runtime.h>
#include <cuda_bf16.h>
#include <stdint.h>

// Problem constants (match reference setup_inputs)
#define TOTAL   262144        // B*N = 16*16384
#define NGROUP  1024          // NUM_GROUPS
#define GSENT   1024          // sentinel group for masked-out nodes
#define NBLK    512           // number of stable-sort chunks
#define CHUNK   512           // TOTAL / NBLK
#define RANK_THREADS 256      // 8 warps; one block per chunk
#define SUBCHUNK     64       // CHUNK / 8 elements per warp
#define LOSS_THREADS 256
#define LOSS_BLOCKS  1024     // 8192 warps
#define CHUNK_T      32       // sorted positions per warp
#define CSCAN_BLOCKS ((NGROUP + 1 + 7) / 8)   // 129 blocks of 8 warps
#define IDX_MASK 0x3FFFF      // low 18 bits = original index

// ---------------- scratch (static __device__, no allocation) ----------------
__device__ int   d_rg[TOTAL];                    // packed (g<<16)|rank
__device__ int   d_histT[(NGROUP + 1) * NBLK];   // [g][b]
__device__ int   d_offT [(NGROUP + 1) * NBLK];   // [g][b] exclusive over b
__device__ int   d_counts[NGROUP + 1];
__device__ int   d_starts[NGROUP + 2];
__device__ int   d_os[TOTAL];                    // packed (g<<18)|origIndex
__device__ float d_partials[2 * LOSS_BLOCKS];
__device__ int   d_done;      // zero-init; last loss block resets to 0
__device__ int   d_csDone;    // zero-init; last colscan block resets to 0

// ---------------- threefry2x32 (JAX partitionable mode) ----------------
__device__ __forceinline__ unsigned rotl32(unsigned v, int d) {
    return (v << d) | (v >> (32 - d));
}

__device__ __forceinline__ void threefry2x32(unsigned k0, unsigned k1,
                                             unsigned& x0, unsigned& x1) {
    const unsigned ks0 = k0, ks1 = k1, ks2 = k0 ^ k1 ^ 0x1BD11BDAu;
    x0 += ks0; x1 += ks1;
#define TF_R4(a,b,c,d)                                  \
    x0 += x1; x1 = rotl32(x1, a); x1 ^= x0;             \
    x0 += x1; x1 = rotl32(x1, b); x1 ^= x0;             \
    x0 += x1; x1 = rotl32(x1, c); x1 ^= x0;             \
    x0 += x1; x1 = rotl32(x1, d); x1 ^= x0;
    TF_R4(13,15,26, 6); x0 += ks1; x1 += ks2 + 1u;
    TF_R4(17,29,16,24); x0 += ks2; x1 += ks0 + 2u;
    TF_R4(13,15,26, 6); x0 += ks0; x1 += ks1 + 3u;
    TF_R4(17,29,16,24); x0 += ks1; x1 += ks2 + 4u;
    TF_R4(13,15,26, 6); x0 += ks2; x1 += ks0 + 5u;
#undef TF_R4
}

// u[t]: counter = 64-bit flat index -> (hi=0, lo=t); draw = fold(out0^out1).
__device__ __forceinline__ float jax_uniform_at(int t) {
    unsigned x0 = 0u;
    unsigned x1 = (unsigned)t;
    threefry2x32(0u, 42u, x0, x1);       // jax.random.key(42) -> (0, 42)
    const unsigned bits = x0 ^ x1;
    return __uint_as_float((bits >> 9) | 0x3f800000u) - 1.0f;
}

// negative sorted-position for sorted index t, given precomputed uniform u
__device__ __forceinline__ int neg_pos_u(float u, int st, int cnt, int valid_total) {
    const int comp = max(valid_total - cnt, 1);
    int r = (int)(u * (float)comp);
    if (r > comp - 1) r = comp - 1;
    int np_ = (r < st) ? r : r + cnt;
    if (np_ < 0) np_ = 0;
    if (np_ > TOTAL - 1) np_ = TOTAL - 1;
    return np_;
}

// ---------------- K1: block-parallel stable rank + per-chunk histogram ----------
__global__ void __launch_bounds__(RANK_THREADS)
rank_kernel(const int* __restrict__ groups, const int* __restrict__ mask) {
    __shared__ int bins[8][NGROUP + 1];      // [warp][group]
    const int warpId = threadIdx.x >> 5;
    const int lane = threadIdx.x & 31;
    const int b = blockIdx.x;                // chunk id 0..511
    for (int i = threadIdx.x; i < 8 * (NGROUP + 1); i += RANK_THREADS)
        ((int*)bins)[i] = 0;
    __syncthreads();

    // phase A: per-warp local rank within its 64-element sub-chunk
    const int base = b * CHUNK + warpId * SUBCHUNK;
    int gReg[2], rReg[2];
    #pragma unroll
    for (int k = 0; k < 2; k++) {
        const int i = base + k * 32 + lane;
        const int g = mask[i] ? groups[i] : GSENT;
        const unsigned m = __match_any_sync(0xffffffffu, g);
        const int rankInWarp = __popc(m & ((1u << lane) - 1u));
        const int leader = __ffs(m) - 1;
        int baseBin = 0;
        if (lane == leader) baseBin = atomicAdd(&bins[warpId][g], __popc(m));
        baseBin = __shfl_sync(0xffffffffu, baseBin, leader);
        gReg[k] = g;
        rReg[k] = baseBin + rankInWarp;
        __syncwarp();
    }
    __syncthreads();

    // phase B: per-group exclusive prefix across the 8 warp bins (in place)
    for (int g = threadIdx.x; g <= NGROUP; g += RANK_THREADS) {
        int c[8], s = 0;
        #pragma unroll
        for (int w = 0; w < 8; w++) { c[w] = bins[w][g]; }
        #pragma unroll
        for (int w = 0; w < 8; w++) { bins[w][g] = s; s += c[w]; }
        d_histT[g * NBLK + b] = s;
    }
    __syncthreads();

    // phase C: emit packed (g, chunk-rank)
    #pragma unroll
    for (int k = 0; k < 2; k++) {
        const int i = base + k * 32 + lane;
        const int g = gReg[k];
        d_rg[i] = (g << 16) | (bins[warpId][g] + rReg[k]);
    }
}

// ---------------- K2: per-group scan over chunks + fused starts scan ------------
__global__ void __launch_bounds__(256)
colscan_kernel() {
    const int warpId = threadIdx.x >> 5;
    const int lane = threadIdx.x & 31;
    const int g = blockIdx.x * 8 + warpId;
    cudaGridDependencySynchronize();         // PDL: wait for rank's histT
    if (g <= NGROUP) {
        const int baseIdx = g * NBLK;
        int cum = 0;
        #pragma unroll
        for (int b0 = 0; b0 < NBLK; b0 += 32) {
            const int h = d_histT[baseIdx + b0 + lane];     // coalesced 128B
            int x = h;
            #pragma unroll
            for (int o = 1; o < 32; o <<= 1) {
                const int y = __shfl_up_sync(0xffffffffu, x, o);
                if (lane >= o) x += y;
            }
            d_offT[baseIdx + b0 + lane] = cum + x - h;      // exclusive
            cum += __shfl_sync(0xffffffffu, x, 31);
        }
        if (lane == 0) d_counts[g] = cum;
    }
    // ---- fused starts: last finishing block's warp 0 scans counts ----
    __shared__ int isLast;
    __syncthreads();
    if (threadIdx.x == 0) {
        __threadfence();
        isLast = (atomicAdd(&d_csDone, 1) == CSCAN_BLOCKS - 1);
    }
    __syncthreads();
    if (isLast && warpId == 0) {
        int cum = 0;
        #pragma unroll 1
        for (int b0 = 0; b0 <= NGROUP; b0 += 32) {
            const int idx = b0 + lane;
            const int v = (idx <= NGROUP) ? *(volatile int*)(d_counts + idx) : 0;
            int x = v;
            #pragma unroll
            for (int o = 1; o < 32; o <<= 1) {
                const int y = __shfl_up_sync(0xffffffffu, x, o);
                if (lane >= o) x += y;
            }
            if (idx <= NGROUP) d_starts[idx] = cum + x - v;   // exclusive
            cum += __shfl_sync(0xffffffffu, x, 31);
        }
        if (lane == 0) d_csDone = 0;          // reset for graph replay
    }
}

// ---------------- K3: stable scatter (packed 4B stores) ------------
__global__ void __launch_bounds__(256)
scatter_kernel() {
    const int i = blockIdx.x * blockDim.x + threadIdx.x;
    cudaGridDependencySynchronize();         // PDL: wait for colscan (and rank)
    if (i >= TOTAL) return;
    const int rg = d_rg[i];
    const int g = rg >> 16;
    const int b = i >> 9;                     // i / CHUNK
    const int pos = d_starts[g] + d_offT[g * NBLK + b] + (rg & 0xffff);
    d_os[pos] = (g << 18) | i;
}

// ---------------- K4: main loss (R8 inner loop; occ-5, packed osg) ------
__global__ void __launch_bounds__(LOSS_THREADS, 5)
loss_kernel(const float4* __restrict__ emb, float* __restrict__ out) {
    const int lane = threadIdx.x & 31;
    const int warpInBlock = threadIdx.x >> 5;
    const int wid = blockIdx.x * (LOSS_THREADS / 32) + warpInBlock;
    const int lo = wid * CHUNK_T;

    // RNG depends only on t: overlap with scatter via PDL early launch
    const float uPre = jax_uniform_at(lo + lane);
    cudaGridDependencySynchronize();         // PDL: wait for scatter's d_os

    const int valid_total = d_starts[NGROUP];

    // ---- per-lane precompute (all 32 lanes) ----
    int anchor, negi, posi, isStart, validL;
    {
        const int t = lo + lane;
        const int og = __ldg(d_os + t);
        anchor = og & IDX_MASK;
        const int g = og >> 18;
        const int st = d_starts[g];
        const int cnt = d_counts[g];
        const int np = neg_pos_u(uPre, st, cnt, valid_total);
        negi = __ldg(d_os + np) & IDX_MASK;
        isStart = (t == st);
        const int pIdx = isStart ? (st + cnt - 1) : (t - 1);
        posi = __ldg(d_os + pIdx) & IDX_MASK;
        validL = (g < NGROUP) && (cnt >= 2) && ((valid_total - cnt) > 0);
    }

    float lsum = 0.0f, wsum = 0.0f;
    float4 aPrev = make_float4(0.f, 0.f, 0.f, 0.f);

    #pragma unroll 1
    for (int tp = 0; tp < CHUNK_T; tp += 4) {
        const unsigned FULL = 0xffffffffu;
        const int a0 = __shfl_sync(FULL, anchor, tp + 0);
        const int a1 = __shfl_sync(FULL, anchor, tp + 1);
        const int a2 = __shfl_sync(FULL, anchor, tp + 2);
        const int a3 = __shfl_sync(FULL, anchor, tp + 3);
        const int q0 = __shfl_sync(FULL, negi, tp + 0);
        const int q1 = __shfl_sync(FULL, negi, tp + 1);
        const int q2 = __shfl_sync(FULL, negi, tp + 2);
        const int q3 = __shfl_sync(FULL, negi, tp + 3);
        const int s0 = __shfl_sync(FULL, isStart, tp + 0);
        const int s1 = __shfl_sync(FULL, isStart, tp + 1);
        const int s2 = __shfl_sync(FULL, isStart, tp + 2);
        const int s3 = __shfl_sync(FULL, isStart, tp + 3);

        const float4 A0 = __ldg(&emb[a0 * 32 + lane]);
        const float4 A1 = __ldg(&emb[a1 * 32 + lane]);
        const float4 A2 = __ldg(&emb[a2 * 32 + lane]);
        const float4 A3 = __ldg(&emb[a3 * 32 + lane]);
        const float4 Q0 = __ldg(&emb[q0 * 32 + lane]);
        const float4 Q1 = __ldg(&emb[q1 * 32 + lane]);
        const float4 Q2 = __ldg(&emb[q2 * 32 + lane]);
        const float4 Q3 = __ldg(&emb[q3 * 32 + lane]);

        float4 P0;
        if (tp == 0 || s0) P0 = __ldg(&emb[__shfl_sync(FULL, posi, tp + 0) * 32 + lane]);
        else               P0 = aPrev;
        float4 P1 = s1 ? __ldg(&emb[__shfl_sync(FULL, posi, tp + 1) * 32 + lane]) : A0;
        float4 P2 = s2 ? __ldg(&emb[__shfl_sync(FULL, posi, tp + 2) * 32 + lane]) : A1;
        float4 P3 = s3 ? __ldg(&emb[__shfl_sync(FULL, posi, tp + 3) * 32 + lane]) : A2;
        aPrev = A3;

        float dp0 = A0.x*P0.x + A0.y*P0.y + A0.z*P0.z + A0.w*P0.w;
        float dn0 = A0.x*Q0.x + A0.y*Q0.y + A0.z*Q0.z + A0.w*Q0.w;
        float dp1 = A1.x*P1.x + A1.y*P1.y + A1.z*P1.z + A1.w*P1.w;
        float dn1 = A1.x*Q1.x + A1.y*Q1.y + A1.z*Q1.z + A1.w*Q1.w;
        float dp2 = A2.x*P2.x + A2.y*P2.y + A2.z*P2.z + A2.w*P2.w;
        float dn2 = A2.x*Q2.x + A2.y*Q2.y + A2.z*Q2.z + A2.w*Q2.w;
        float dp3 = A3.x*P3.x + A3.y*P3.y + A3.z*P3.z + A3.w*P3.w;
        float dn3 = A3.x*Q3.x + A3.y*Q3.y + A3.z*Q3.z + A3.w*Q3.w;
        #pragma unroll
        for (int o = 16; o; o >>= 1) {
            dp0 += __shfl_xor_sync(FULL, dp0, o);
            dn0 += __shfl_xor_sync(FULL, dn0, o);
            dp1 += __shfl_xor_sync(FULL, dp1, o);
            dn1 += __shfl_xor_sync(FULL, dn1, o);
            dp2 += __shfl_xor_sync(FULL, dp2, o);
            dn2 += __shfl_xor_sync(FULL, dn2, o);
            dp3 += __shfl_xor_sync(FULL, dp3, o);
            dn3 += __shfl_xor_sync(FULL, dn3, o);
        }

        // lanes 0..3 finish their own t in parallel
        const int vv = __shfl_sync(FULL, validL, tp + (lane & 3));
        if (lane < 4 && vv) {
            float dd;
            if      (lane == 0) dd = dn0 - dp0;
            else if (lane == 1) dd = dn1 - dp1;
            else if (lane == 2) dd = dn2 - dp2;
            else                dd = dn3 - dp3;
            dd *= 10.0f;                         // / TEMPERATURE
            lsum += fmaxf(dd, 0.0f) + log1pf(expf(-fabsf(dd)));
            wsum += 1.0f;
        }
    }

    // warp-reduce the lane-distributed sums
    #pragma unroll
    for (int o = 16; o; o >>= 1) {
        lsum += __shfl_xor_sync(0xffffffffu, lsum, o);
        wsum += __shfl_xor_sync(0xffffffffu, wsum, o);
    }

    // deterministic block reduction
    __shared__ float sl[LOSS_THREADS / 32];
    __shared__ float sw[LOSS_THREADS / 32];
    __shared__ int isLast;
    if (lane == 0) { sl[warpInBlock] = lsum; sw[warpInBlock] = wsum; }
    __syncthreads();
    if (threadIdx.x == 0) {
        float L = 0.0f, W = 0.0f;
        #pragma unroll
        for (int i = 0; i < LOSS_THREADS / 32; i++) { L += sl[i]; W += sw[i]; }
        d_partials[2 * blockIdx.x]     = L;
        d_partials[2 * blockIdx.x + 1] = W;
        __threadfence();
        isLast = (atomicAdd(&d_done, 1) == LOSS_BLOCKS - 1);
    }
    __syncthreads();

    // last finishing block does the deterministic final reduction
    if (isLast) {
        __shared__ float fl[256];
        __shared__ float fw[256];
        float L = 0.0f, W = 0.0f;
        for (int i = threadIdx.x; i < LOSS_BLOCKS; i += 256) {
            L += *(volatile float*)(d_partials + 2 * i);
            W += *(volatile float*)(d_partials + 2 * i + 1);
        }
        fl[threadIdx.x] = L; fw[threadIdx.x] = W;
        __syncthreads();
        for (int s = 128; s > 0; s >>= 1) {
            if (threadIdx.x < s) {
                fl[threadIdx.x] += fl[threadIdx.x + s];
                fw[threadIdx.x] += fw[threadIdx.x + s];
            }
            __syncthreads();
        }
        if (threadIdx.x == 0) {
            out[0] = fl[0] / fmaxf(fw[0], 1.0f);
            d_done = 0;                       // reset for graph replay
        }
    }
}

// ---------------- launch (PDL: overlap dependent-kernel launch with producer) ----
static inline void launch_pdl(void (*kern)(), dim3 grid, dim3 block) {
    cudaLaunchConfig_t cfg = {};
    cfg.gridDim = grid;
    cfg.blockDim = block;
    cudaLaunchAttribute attr[1];
    attr[0].id = cudaLaunchAttributeProgrammaticStreamSerialization;
    attr[0].val.programmaticStreamSerializationAllowed = 1;
    cfg.attrs = attr;
    cfg.numAttrs = 1;
    cudaLaunchKernelEx(&cfg, kern);
}

extern "C" void kernel_launch(void* const* d_in, const int* in_sizes, int n_in,
                              void* d_out, int out_size) {
    const float4* emb   = (const float4*)d_in[0];
    const int*    grp   = (const int*)d_in[1];
    const int*    mask  = (const int*)d_in[2];
    float*        out   = (float*)d_out;
    (void)in_sizes; (void)n_in; (void)out_size;

    rank_kernel<<<NBLK, RANK_THREADS>>>(grp, mask);
    launch_pdl(colscan_kernel, dim3(CSCAN_BLOCKS), dim3(256));
    launch_pdl(scatter_kernel, dim3(TOTAL / 256), dim3(256));
    {
        cudaLaunchConfig_t cfg = {};
        cfg.gridDim = dim3(LOSS_BLOCKS);
        cfg.blockDim = dim3(LOSS_THREADS);
        cudaLaunchAttribute attr[1];
        attr[0].id = cudaLaunchAttributeProgrammaticStreamSerialization;
        attr[0].val.programmaticStreamSerializationAllowed = 1;
        cfg.attrs = attr;
        cfg.numAttrs = 1;
        cudaLaunchKernelEx(&cfg, loss_kernel, emb, out);
    }
}

// round 16
// speedup vs baseline: 1.1622x; 1.1622x over previous
#include <cuda_runtime.h>
#include <cuda_bf16.h>
#include <stdint.h>

// Problem constants (match reference setup_inputs)
#define TOTAL   262144        // B*N = 16*16384
#define NGROUP  1024          // NUM_GROUPS
#define GSENT   1024          // sentinel group for masked-out nodes
#define NBLK    512           // number of stable-sort chunks
#define CHUNK   512           // TOTAL / NBLK
#define RANK_THREADS 256      // 8 warps; one block per chunk
#define SUBCHUNK     64       // CHUNK / 8 elements per warp
#define LOSS_THREADS 256
#define LOSS_BLOCKS  1024     // 8192 warps
#define CHUNK_T      32       // sorted positions per warp
#define CSCAN_BLOCKS ((NGROUP + 1 + 7) / 8)   // 129 blocks of 8 warps
#define IDX_MASK 0x3FFFF      // low 18 bits = original index

// ---------------- scratch (static __device__, no allocation) ----------------
__device__ int   d_rg[TOTAL];                    // packed (g<<16)|rank
__device__ int   d_histT[(NGROUP + 1) * NBLK];   // [g][b]
__device__ int   d_offT [(NGROUP + 1) * NBLK];   // [g][b] exclusive over b
__device__ int   d_counts[NGROUP + 1];
__device__ int   d_starts[NGROUP + 2];
__device__ int   d_os[TOTAL];                    // packed (g<<18)|origIndex
__device__ float d_partials[2 * LOSS_BLOCKS];
__device__ int   d_done;      // zero-init; last loss block resets to 0
__device__ int   d_csDone;    // zero-init; last colscan block resets to 0

// ---------------- threefry2x32 (JAX partitionable mode) ----------------
__device__ __forceinline__ unsigned rotl32(unsigned v, int d) {
    return (v << d) | (v >> (32 - d));
}

__device__ __forceinline__ void threefry2x32(unsigned k0, unsigned k1,
                                             unsigned& x0, unsigned& x1) {
    const unsigned ks0 = k0, ks1 = k1, ks2 = k0 ^ k1 ^ 0x1BD11BDAu;
    x0 += ks0; x1 += ks1;
#define TF_R4(a,b,c,d)                                  \
    x0 += x1; x1 = rotl32(x1, a); x1 ^= x0;             \
    x0 += x1; x1 = rotl32(x1, b); x1 ^= x0;             \
    x0 += x1; x1 = rotl32(x1, c); x1 ^= x0;             \
    x0 += x1; x1 = rotl32(x1, d); x1 ^= x0;
    TF_R4(13,15,26, 6); x0 += ks1; x1 += ks2 + 1u;
    TF_R4(17,29,16,24); x0 += ks2; x1 += ks0 + 2u;
    TF_R4(13,15,26, 6); x0 += ks0; x1 += ks1 + 3u;
    TF_R4(17,29,16,24); x0 += ks1; x1 += ks2 + 4u;
    TF_R4(13,15,26, 6); x0 += ks2; x1 += ks0 + 5u;
#undef TF_R4
}

// u[t]: counter = 64-bit flat index -> (hi=0, lo=t); draw = fold(out0^out1).
__device__ __forceinline__ float jax_uniform_at(int t) {
    unsigned x0 = 0u;
    unsigned x1 = (unsigned)t;
    threefry2x32(0u, 42u, x0, x1);       // jax.random.key(42) -> (0, 42)
    const unsigned bits = x0 ^ x1;
    return __uint_as_float((bits >> 9) | 0x3f800000u) - 1.0f;
}

// negative sorted-position for sorted index t, given precomputed uniform u
__device__ __forceinline__ int neg_pos_u(float u, int st, int cnt, int valid_total) {
    const int comp = max(valid_total - cnt, 1);
    int r = (int)(u * (float)comp);
    if (r > comp - 1) r = comp - 1;
    int np_ = (r < st) ? r : r + cnt;
    if (np_ < 0) np_ = 0;
    if (np_ > TOTAL - 1) np_ = TOTAL - 1;
    return np_;
}

// ---------------- K1: block-parallel stable rank + per-chunk histogram ----------
__global__ void __launch_bounds__(RANK_THREADS)
rank_kernel(const int* __restrict__ groups, const int* __restrict__ mask) {
    __shared__ int bins[8][NGROUP + 1];      // [warp][group]
    const int warpId = threadIdx.x >> 5;
    const int lane = threadIdx.x & 31;
    const int b = blockIdx.x;                // chunk id 0..511
    for (int i = threadIdx.x; i < 8 * (NGROUP + 1); i += RANK_THREADS)
        ((int*)bins)[i] = 0;
    __syncthreads();

    // phase A: per-warp local rank within its 64-element sub-chunk
    const int base = b * CHUNK + warpId * SUBCHUNK;
    int gReg[2], rReg[2];
    #pragma unroll
    for (int k = 0; k < 2; k++) {
        const int i = base + k * 32 + lane;
        const int g = mask[i] ? groups[i] : GSENT;
        const unsigned m = __match_any_sync(0xffffffffu, g);
        const int rankInWarp = __popc(m & ((1u << lane) - 1u));
        const int leader = __ffs(m) - 1;
        int baseBin = 0;
        if (lane == leader) baseBin = atomicAdd(&bins[warpId][g], __popc(m));
        baseBin = __shfl_sync(0xffffffffu, baseBin, leader);
        gReg[k] = g;
        rReg[k] = baseBin + rankInWarp;
        __syncwarp();
    }
    __syncthreads();

    // phase B: per-group exclusive prefix across the 8 warp bins (in place)
    for (int g = threadIdx.x; g <= NGROUP; g += RANK_THREADS) {
        int c[8], s = 0;
        #pragma unroll
        for (int w = 0; w < 8; w++) { c[w] = bins[w][g]; }
        #pragma unroll
        for (int w = 0; w < 8; w++) { bins[w][g] = s; s += c[w]; }
        d_histT[g * NBLK + b] = s;
    }
    __syncthreads();

    // phase C: emit packed (g, chunk-rank)
    #pragma unroll
    for (int k = 0; k < 2; k++) {
        const int i = base + k * 32 + lane;
        const int g = gReg[k];
        d_rg[i] = (g << 16) | (bins[warpId][g] + rReg[k]);
    }
}

// ---------------- K2: per-group scan over chunks + fused starts scan ------------
__global__ void __launch_bounds__(256)
colscan_kernel() {
    const int warpId = threadIdx.x >> 5;
    const int lane = threadIdx.x & 31;
    const int g = blockIdx.x * 8 + warpId;
    cudaGridDependencySynchronize();         // PDL: wait for rank's histT
    if (g <= NGROUP) {
        const int baseIdx = g * NBLK;
        int cum = 0;
        #pragma unroll
        for (int b0 = 0; b0 < NBLK; b0 += 32) {
            const int h = d_histT[baseIdx + b0 + lane];     // coalesced 128B
            int x = h;
            #pragma unroll
            for (int o = 1; o < 32; o <<= 1) {
                const int y = __shfl_up_sync(0xffffffffu, x, o);
                if (lane >= o) x += y;
            }
            d_offT[baseIdx + b0 + lane] = cum + x - h;      // exclusive
            cum += __shfl_sync(0xffffffffu, x, 31);
        }
        if (lane == 0) d_counts[g] = cum;
    }
    // ---- fused starts: last finishing block's warp 0 scans counts ----
    __shared__ int isLast;
    __syncthreads();
    if (threadIdx.x == 0) {
        __threadfence();
        isLast = (atomicAdd(&d_csDone, 1) == CSCAN_BLOCKS - 1);
    }
    __syncthreads();
    if (isLast && warpId == 0) {
        int cum = 0;
        #pragma unroll 1
        for (int b0 = 0; b0 <= NGROUP; b0 += 32) {
            const int idx = b0 + lane;
            const int v = (idx <= NGROUP) ? *(volatile int*)(d_counts + idx) : 0;
            int x = v;
            #pragma unroll
            for (int o = 1; o < 32; o <<= 1) {
                const int y = __shfl_up_sync(0xffffffffu, x, o);
                if (lane >= o) x += y;
            }
            if (idx <= NGROUP) d_starts[idx] = cum + x - v;   // exclusive
            cum += __shfl_sync(0xffffffffu, x, 31);
        }
        if (lane == 0) d_csDone = 0;          // reset for graph replay
    }
}

// ---------------- K3: stable scatter (packed 4B stores) ------------
__global__ void __launch_bounds__(256)
scatter_kernel() {
    const int i = blockIdx.x * blockDim.x + threadIdx.x;
    cudaGridDependencySynchronize();         // PDL: wait for colscan (and rank)
    if (i >= TOTAL) return;
    const int rg = d_rg[i];
    const int g = rg >> 16;
    const int b = i >> 9;                     // i / CHUNK
    const int pos = d_starts[g] + d_offT[g * NBLK + b] + (rg & 0xffff);
    d_os[pos] = (g << 18) | i;
}

// ---------------- K4: main loss (R8 inner loop; natural regs; packed d_os) ------
__global__ void __launch_bounds__(LOSS_THREADS)
loss_kernel(const float4* __restrict__ emb, float* __restrict__ out) {
    const int lane = threadIdx.x & 31;
    const int warpInBlock = threadIdx.x >> 5;
    const int wid = blockIdx.x * (LOSS_THREADS / 32) + warpInBlock;
    const int lo = wid * CHUNK_T;

    // RNG depends only on t: overlap with scatter via PDL early launch
    const float uPre = jax_uniform_at(lo + lane);
    cudaGridDependencySynchronize();         // PDL: wait for scatter's d_os

    const int valid_total = d_starts[NGROUP];

    // ---- per-lane precompute (all 32 lanes) ----
    int anchor, negi, posi, isStart, validL;
    {
        const int t = lo + lane;
        const int og = __ldg(d_os + t);
        anchor = og & IDX_MASK;
        const int g = og >> 18;
        const int st = d_starts[g];
        const int cnt = d_counts[g];
        const int np = neg_pos_u(uPre, st, cnt, valid_total);
        negi = __ldg(d_os + np) & IDX_MASK;
        isStart = (t == st);
        const int pIdx = isStart ? (st + cnt - 1) : (t - 1);
        posi = __ldg(d_os + pIdx) & IDX_MASK;
        validL = (g < NGROUP) && (cnt >= 2) && ((valid_total - cnt) > 0);
    }

    float lsum = 0.0f, wsum = 0.0f;
    float4 aPrev = make_float4(0.f, 0.f, 0.f, 0.f);

    #pragma unroll 1
    for (int tp = 0; tp < CHUNK_T; tp += 4) {
        const unsigned FULL = 0xffffffffu;
        const int a0 = __shfl_sync(FULL, anchor, tp + 0);
        const int a1 = __shfl_sync(FULL, anchor, tp + 1);
        const int a2 = __shfl_sync(FULL, anchor, tp + 2);
        const int a3 = __shfl_sync(FULL, anchor, tp + 3);
        const int q0 = __shfl_sync(FULL, negi, tp + 0);
        const int q1 = __shfl_sync(FULL, negi, tp + 1);
        const int q2 = __shfl_sync(FULL, negi, tp + 2);
        const int q3 = __shfl_sync(FULL, negi, tp + 3);
        const int s0 = __shfl_sync(FULL, isStart, tp + 0);
        const int s1 = __shfl_sync(FULL, isStart, tp + 1);
        const int s2 = __shfl_sync(FULL, isStart, tp + 2);
        const int s3 = __shfl_sync(FULL, isStart, tp + 3);

        const float4 A0 = __ldg(&emb[a0 * 32 + lane]);
        const float4 A1 = __ldg(&emb[a1 * 32 + lane]);
        const float4 A2 = __ldg(&emb[a2 * 32 + lane]);
        const float4 A3 = __ldg(&emb[a3 * 32 + lane]);
        const float4 Q0 = __ldg(&emb[q0 * 32 + lane]);
        const float4 Q1 = __ldg(&emb[q1 * 32 + lane]);
        const float4 Q2 = __ldg(&emb[q2 * 32 + lane]);
        const float4 Q3 = __ldg(&emb[q3 * 32 + lane]);

        float4 P0;
        if (tp == 0 || s0) P0 = __ldg(&emb[__shfl_sync(FULL, posi, tp + 0) * 32 + lane]);
        else               P0 = aPrev;
        float4 P1 = s1 ? __ldg(&emb[__shfl_sync(FULL, posi, tp + 1) * 32 + lane]) : A0;
        float4 P2 = s2 ? __ldg(&emb[__shfl_sync(FULL, posi, tp + 2) * 32 + lane]) : A1;
        float4 P3 = s3 ? __ldg(&emb[__shfl_sync(FULL, posi, tp + 3) * 32 + lane]) : A2;
        aPrev = A3;

        float dp0 = A0.x*P0.x + A0.y*P0.y + A0.z*P0.z + A0.w*P0.w;
        float dn0 = A0.x*Q0.x + A0.y*Q0.y + A0.z*Q0.z + A0.w*Q0.w;
        float dp1 = A1.x*P1.x + A1.y*P1.y + A1.z*P1.z + A1.w*P1.w;
        float dn1 = A1.x*Q1.x + A1.y*Q1.y + A1.z*Q1.z + A1.w*Q1.w;
        float dp2 = A2.x*P2.x + A2.y*P2.y + A2.z*P2.z + A2.w*P2.w;
        float dn2 = A2.x*Q2.x + A2.y*Q2.y + A2.z*Q2.z + A2.w*Q2.w;
        float dp3 = A3.x*P3.x + A3.y*P3.y + A3.z*P3.z + A3.w*P3.w;
        float dn3 = A3.x*Q3.x + A3.y*Q3.y + A3.z*Q3.z + A3.w*Q3.w;
        #pragma unroll
        for (int o = 16; o; o >>= 1) {
            dp0 += __shfl_xor_sync(FULL, dp0, o);
            dn0 += __shfl_xor_sync(FULL, dn0, o);
            dp1 += __shfl_xor_sync(FULL, dp1, o);
            dn1 += __shfl_xor_sync(FULL, dn1, o);
            dp2 += __shfl_xor_sync(FULL, dp2, o);
            dn2 += __shfl_xor_sync(FULL, dn2, o);
            dp3 += __shfl_xor_sync(FULL, dp3, o);
            dn3 += __shfl_xor_sync(FULL, dn3, o);
        }

        // lanes 0..3 finish their own t in parallel
        const int vv = __shfl_sync(FULL, validL, tp + (lane & 3));
        if (lane < 4 && vv) {
            float dd;
            if      (lane == 0) dd = dn0 - dp0;
            else if (lane == 1) dd = dn1 - dp1;
            else if (lane == 2) dd = dn2 - dp2;
            else                dd = dn3 - dp3;
            dd *= 10.0f;                         // / TEMPERATURE
            lsum += fmaxf(dd, 0.0f) + log1pf(expf(-fabsf(dd)));
            wsum += 1.0f;
        }
    }

    // warp-reduce the lane-distributed sums
    #pragma unroll
    for (int o = 16; o; o >>= 1) {
        lsum += __shfl_xor_sync(0xffffffffu, lsum, o);
        wsum += __shfl_xor_sync(0xffffffffu, wsum, o);
    }

    // deterministic block reduction
    __shared__ float sl[LOSS_THREADS / 32];
    __shared__ float sw[LOSS_THREADS / 32];
    __shared__ int isLast;
    if (lane == 0) { sl[warpInBlock] = lsum; sw[warpInBlock] = wsum; }
    __syncthreads();
    if (threadIdx.x == 0) {
        float L = 0.0f, W = 0.0f;
        #pragma unroll
        for (int i = 0; i < LOSS_THREADS / 32; i++) { L += sl[i]; W += sw[i]; }
        d_partials[2 * blockIdx.x]     = L;
        d_partials[2 * blockIdx.x + 1] = W;
        __threadfence();
        isLast = (atomicAdd(&d_done, 1) == LOSS_BLOCKS - 1);
    }
    __syncthreads();

    // last finishing block does the deterministic final reduction
    if (isLast) {
        __shared__ float fl[256];
        __shared__ float fw[256];
        float L = 0.0f, W = 0.0f;
        for (int i = threadIdx.x; i < LOSS_BLOCKS; i += 256) {
            L += *(volatile float*)(d_partials + 2 * i);
            W += *(volatile float*)(d_partials + 2 * i + 1);
        }
        fl[threadIdx.x] = L; fw[threadIdx.x] = W;
        __syncthreads();
        for (int s = 128; s > 0; s >>= 1) {
            if (threadIdx.x < s) {
                fl[threadIdx.x] += fl[threadIdx.x + s];
                fw[threadIdx.x] += fw[threadIdx.x + s];
            }
            __syncthreads();
        }
        if (threadIdx.x == 0) {
            out[0] = fl[0] / fmaxf(fw[0], 1.0f);
            d_done = 0;                       // reset for graph replay
        }
    }
}

// ---------------- launch (PDL: overlap dependent-kernel launch with producer) ----
static inline void launch_pdl(void (*kern)(), dim3 grid, dim3 block) {
    cudaLaunchConfig_t cfg = {};
    cfg.gridDim = grid;
    cfg.blockDim = block;
    cudaLaunchAttribute attr[1];
    attr[0].id = cudaLaunchAttributeProgrammaticStreamSerialization;
    attr[0].val.programmaticStreamSerializationAllowed = 1;
    cfg.attrs = attr;
    cfg.numAttrs = 1;
    cudaLaunchKernelEx(&cfg, kern);
}

extern "C" void kernel_launch(void* const* d_in, const int* in_sizes, int n_in,
                              void* d_out, int out_size) {
    const float4* emb   = (const float4*)d_in[0];
    const int*    grp   = (const int*)d_in[1];
    const int*    mask  = (const int*)d_in[2];
    float*        out   = (float*)d_out;
    (void)in_sizes; (void)n_in; (void)out_size;

    rank_kernel<<<NBLK, RANK_THREADS>>>(grp, mask);
    launch_pdl(colscan_kernel, dim3(CSCAN_BLOCKS), dim3(256));
    launch_pdl(scatter_kernel, dim3(TOTAL / 256), dim3(256));
    {
        cudaLaunchConfig_t cfg = {};
        cfg.gridDim = dim3(LOSS_BLOCKS);
        cfg.blockDim = dim3(LOSS_THREADS);
        cudaLaunchAttribute attr[1];
        attr[0].id = cudaLaunchAttributeProgrammaticStreamSerialization;
        attr[0].val.programmaticStreamSerializationAllowed = 1;
        cfg.attrs = attr;
        cfg.numAttrs = 1;
        cudaLaunchKernelEx(&cfg, loss_kernel, emb, out);
    }
}